// round 2
// baseline (speedup 1.0000x reference)
#include <cuda_runtime.h>
#include <cuda_fp16.h>
#include <cstdint>
#include <cstddef>

#define BATCH 4096
#define OBS   512
#define ACT   32
#define H1D   1024
#define H2D   1024

// ---------------- static device scratch (no allocations) ----------------
static __device__ __align__(256) __half g_obs[(size_t)BATCH * OBS];           //   4 MB
static __device__ __align__(256) __half g_W1 [(size_t)ACT * OBS * H1D];       //  32 MB
static __device__ __align__(256) __half g_W2 [(size_t)ACT * H1D * H2D];       //  64 MB
static __device__ __align__(256) __half g_x1 [(size_t)ACT * BATCH * H1D];     // 256 MB
static __device__ __align__(256) __half g_x2 [(size_t)ACT * BATCH * H2D];     // 256 MB

// ---------------- PTX helpers ----------------
__device__ __forceinline__ uint32_t s32(const void* p) {
    return (uint32_t)__cvta_generic_to_shared(p);
}
__device__ __forceinline__ void ldm_x4(uint32_t* r, uint32_t a) {
    asm volatile("ldmatrix.sync.aligned.m8n8.x4.shared.b16 {%0,%1,%2,%3}, [%4];"
                 : "=r"(r[0]), "=r"(r[1]), "=r"(r[2]), "=r"(r[3]) : "r"(a));
}
__device__ __forceinline__ void ldm_x4t(uint32_t* r, uint32_t a) {
    asm volatile("ldmatrix.sync.aligned.m8n8.x4.trans.shared.b16 {%0,%1,%2,%3}, [%4];"
                 : "=r"(r[0]), "=r"(r[1]), "=r"(r[2]), "=r"(r[3]) : "r"(a));
}
__device__ __forceinline__ void mma16816(float* d, const uint32_t* a, uint32_t b0, uint32_t b1) {
    asm volatile("mma.sync.aligned.m16n8k16.row.col.f32.f16.f16.f32 "
                 "{%0,%1,%2,%3}, {%4,%5,%6,%7}, {%8,%9}, {%0,%1,%2,%3};"
                 : "+f"(d[0]), "+f"(d[1]), "+f"(d[2]), "+f"(d[3])
                 : "r"(a[0]), "r"(a[1]), "r"(a[2]), "r"(a[3]), "r"(b0), "r"(b1));
}
__device__ __forceinline__ void cpa16(uint32_t dst, const void* src) {
    asm volatile("cp.async.cg.shared.global [%0], [%1], 16;" :: "r"(dst), "l"(src));
}
__device__ __forceinline__ void cpa_commit() { asm volatile("cp.async.commit_group;"); }

// ---------------- fp32 -> fp16 conversion into static scratch ----------------
__global__ void f2h_kernel(const float* __restrict__ s, int sel, int n) {
    __half* d = (sel == 0) ? g_obs : ((sel == 1) ? g_W1 : g_W2);
    int i = (blockIdx.x * blockDim.x + threadIdx.x) * 4;
    if (i >= n) return;
    float4 v = *(const float4*)(s + i);
    __half2 h0 = __floats2half2_rn(v.x, v.y);
    __half2 h1 = __floats2half2_rn(v.z, v.w);
    *(__half2*)(d + i)     = h0;
    *(__half2*)(d + i + 2) = h1;
}

// ---------------- batched GEMM + bias + tanh (fp16 in, fp32 accum, fp16 out) ----
// C[a] = tanh(A[a] (MxK) @ W[a] (KxN=1024) + bias[a]),  M = 4096, grid (8, 32, 32)
// Tile: 128x128x32, 256 threads, 8 warps as 4(m) x 2(n), warp tile 32x64.
template <int K, bool L1>
__global__ void __launch_bounds__(256, 2) gemm_kernel(const float* __restrict__ bias) {
    constexpr int BK = 32;
    __shared__ __half sA[2][128][BK + 8];     // 80B row stride: conflict-free ldmatrix
    __shared__ __half sB[2][BK][128 + 8];     // 272B row stride: conflict-free
    __shared__ float  sBias[128];

    const int a  = blockIdx.z;
    const int m0 = blockIdx.y * 128;
    const int n0 = blockIdx.x * 128;

    const __half* A  = L1 ? (g_obs + (size_t)m0 * K)
                          : (g_x1 + ((size_t)a * BATCH + m0) * K);
    const __half* Bw = (L1 ? g_W1 : g_W2) + (size_t)a * K * 1024 + n0;
    __half*       C  = (L1 ? g_x1 : g_x2) + ((size_t)a * BATCH + m0) * 1024 + n0;

    const int t = threadIdx.x;
    if (t < 128) sBias[t] = bias[a * 1024 + n0 + t];

    auto load = [&](int s, int kt) {
#pragma unroll
        for (int i = 0; i < 2; i++) {                       // A: 128 rows x 32 halves
            int c = t + i * 256;
            int r = c >> 2, c8 = (c & 3) * 8;
            cpa16(s32(&sA[s][r][c8]), A + (size_t)r * K + kt + c8);
        }
#pragma unroll
        for (int i = 0; i < 2; i++) {                       // B: 32 rows x 128 halves
            int c = t + i * 256;
            int r = c >> 4, c8 = (c & 15) * 8;
            cpa16(s32(&sB[s][r][c8]), Bw + (size_t)(kt + r) * 1024 + c8);
        }
        cpa_commit();
    };

    const int lane = t & 31, warp = t >> 5;
    const int wm = warp >> 1, wn = warp & 1;

    float acc[2][8][4];
#pragma unroll
    for (int mi = 0; mi < 2; mi++)
#pragma unroll
        for (int ni = 0; ni < 8; ni++)
#pragma unroll
            for (int k = 0; k < 4; k++) acc[mi][ni][k] = 0.f;

    load(0, 0);
    constexpr int NK = K / BK;

    const int lrow  = lane & 15;             // A ldmatrix row within 16
    const int lc8   = (lane >> 4) * 8;       // A ldmatrix col half (0 / 8)
    const int bkrow = lane & 7;              // B ldmatrix row within 8
    const int bk8   = ((lane >> 3) & 1) * 8; // B k-sub (matrix 1/3)
    const int bn8   = (lane >> 4) * 8;       // B n-sub (matrix 2/3)

    for (int kt = 0; kt < NK; kt++) {
        const int s = kt & 1;
        if (kt + 1 < NK) {
            load(s ^ 1, (kt + 1) * BK);
            asm volatile("cp.async.wait_group 1;");
        } else {
            asm volatile("cp.async.wait_group 0;");
        }
        __syncthreads();

#pragma unroll
        for (int ks = 0; ks < 2; ks++) {                 // two k16 steps per BK
            uint32_t af[2][4];
#pragma unroll
            for (int mi = 0; mi < 2; mi++)
                ldm_x4(af[mi], s32(&sA[s][wm * 32 + mi * 16 + lrow][ks * 16 + lc8]));
            uint32_t bf[4][4];
#pragma unroll
            for (int np = 0; np < 4; np++)
                ldm_x4t(bf[np], s32(&sB[s][ks * 16 + bk8 + bkrow][wn * 64 + np * 16 + bn8]));
#pragma unroll
            for (int mi = 0; mi < 2; mi++)
#pragma unroll
                for (int ni = 0; ni < 8; ni++) {
                    int np = ni >> 1, h = (ni & 1) * 2;
                    mma16816(acc[mi][ni], af[mi], bf[np][h], bf[np][h + 1]);
                }
        }
        __syncthreads();
    }

    // epilogue: + bias, tanh, pack fp16, store
#pragma unroll
    for (int mi = 0; mi < 2; mi++) {
        int r0 = wm * 32 + mi * 16 + (lane >> 2);
#pragma unroll
        for (int ni = 0; ni < 8; ni++) {
            int cl = wn * 64 + ni * 8 + (lane & 3) * 2;
            float b0 = sBias[cl], b1 = sBias[cl + 1];
            float* d = acc[mi][ni];
            __half2 h0 = __floats2half2_rn(tanhf(d[0] + b0), tanhf(d[1] + b1));
            __half2 h1 = __floats2half2_rn(tanhf(d[2] + b0), tanhf(d[3] + b1));
            *(__half2*)(C + (size_t)r0 * 1024 + cl)       = h0;
            *(__half2*)(C + (size_t)(r0 + 8) * 1024 + cl) = h1;
        }
    }
}

// ---------------- layer 3: mu[b][a] = dot(x2[a][b][:], W3[a][:]) + b3[a] ------
__global__ void mu_kernel(const float* __restrict__ W3, const float* __restrict__ b3,
                          float* __restrict__ mu) {
    int gw   = (blockIdx.x * blockDim.x + threadIdx.x) >> 5;   // 0 .. 4096*32-1
    int lane = threadIdx.x & 31;
    int b = gw >> 5;
    int a = gw & 31;
    const __half* xr = g_x2 + ((size_t)a * BATCH + b) * 1024;
    const float*  wr = W3 + a * 1024;
    float acc = 0.f;
#pragma unroll
    for (int i = 0; i < 4; i++) {
        int off = (i * 32 + lane) * 8;
        float4 hv = *(const float4*)(xr + off);                 // 8 halves
        const __half2* h = (const __half2*)&hv;
        float4 w0 = *(const float4*)(wr + off);
        float4 w1 = *(const float4*)(wr + off + 4);
        float2 f;
        f = __half22float2(h[0]); acc = fmaf(f.x, w0.x, fmaf(f.y, w0.y, acc));
        f = __half22float2(h[1]); acc = fmaf(f.x, w0.z, fmaf(f.y, w0.w, acc));
        f = __half22float2(h[2]); acc = fmaf(f.x, w1.x, fmaf(f.y, w1.y, acc));
        f = __half22float2(h[3]); acc = fmaf(f.x, w1.z, fmaf(f.y, w1.w, acc));
    }
#pragma unroll
    for (int o = 16; o; o >>= 1) acc += __shfl_xor_sync(0xffffffffu, acc, o);
    if (lane == 0) mu[(size_t)b * 32 + a] = acc + b3[a];
}

// ---------------- logp --------------------------------------------------------
__global__ void logp_kernel(const float* __restrict__ mu, const float* __restrict__ act,
                            const float* __restrict__ ls, float* __restrict__ lp) {
    int b = blockIdx.x * blockDim.x + threadIdx.x;
    if (b >= BATCH) return;
    float s = 0.f;
#pragma unroll
    for (int a = 0; a < 32; a++) {
        float l = ls[a];
        float z = (act[b * 32 + a] - mu[b * 32 + a]) * expf(-l);
        s += -0.5f * (z * z + 1.8378770664093453f) - l;
    }
    lp[b] = s;
}

// ---------------- launch ------------------------------------------------------
extern "C" void kernel_launch(void* const* d_in, const int* in_sizes, int n_in,
                              void* d_out, int out_size) {
    const float* obs  = (const float*)d_in[0];
    const float* act  = (const float*)d_in[1];
    const float* W1   = (const float*)d_in[2];
    const float* b1   = (const float*)d_in[3];
    const float* W2   = (const float*)d_in[4];
    const float* b2   = (const float*)d_in[5];
    const float* W3   = (const float*)d_in[6];
    const float* b3   = (const float*)d_in[7];
    const float* lstd = (const float*)d_in[8];

    float* out = (float*)d_out;
    float* mu  = out;                              // [4096][32]
    float* lp  = out + (size_t)BATCH * ACT;        // [4096]

    f2h_kernel<<<(BATCH * OBS) / 1024, 256>>>(obs, 0, BATCH * OBS);
    f2h_kernel<<<(ACT * OBS * H1D) / 1024, 256>>>(W1, 1, ACT * OBS * H1D);
    f2h_kernel<<<(ACT * H1D * H2D) / 1024, 256>>>(W2, 2, ACT * H1D * H2D);

    gemm_kernel<OBS, true><<<dim3(8, 32, 32), 256>>>(b1);
    gemm_kernel<H1D, false><<<dim3(8, 32, 32), 256>>>(b2);

    mu_kernel<<<(BATCH * ACT * 32) / 256, 256>>>(W3, b3, mu);
    logp_kernel<<<(BATCH + 255) / 256, 256>>>(mu, act, lstd, lp);
}

// round 3
// speedup vs baseline: 1.0580x; 1.0580x over previous
#include <cuda_runtime.h>
#include <cuda_fp16.h>
#include <cstdint>
#include <cstddef>

#define BATCH 4096
#define OBS   512
#define ACT   32
#define H1D   1024
#define H2D   1024

// ---------------- static device scratch (no allocations) ----------------
static __device__ __align__(256) __half g_obs[(size_t)BATCH * OBS];           //   4 MB
static __device__ __align__(256) __half g_W1 [(size_t)ACT * OBS * H1D];       //  32 MB
static __device__ __align__(256) __half g_W2 [(size_t)ACT * H1D * H2D];       //  64 MB
static __device__ __align__(256) __half g_x1 [(size_t)ACT * BATCH * H1D];     // 256 MB

// ---------------- PTX helpers ----------------
__device__ __forceinline__ uint32_t s32(const void* p) {
    return (uint32_t)__cvta_generic_to_shared(p);
}
__device__ __forceinline__ void ldm_x4(uint32_t* r, uint32_t a) {
    asm volatile("ldmatrix.sync.aligned.m8n8.x4.shared.b16 {%0,%1,%2,%3}, [%4];"
                 : "=r"(r[0]), "=r"(r[1]), "=r"(r[2]), "=r"(r[3]) : "r"(a));
}
__device__ __forceinline__ void ldm_x4t(uint32_t* r, uint32_t a) {
    asm volatile("ldmatrix.sync.aligned.m8n8.x4.trans.shared.b16 {%0,%1,%2,%3}, [%4];"
                 : "=r"(r[0]), "=r"(r[1]), "=r"(r[2]), "=r"(r[3]) : "r"(a));
}
__device__ __forceinline__ void mma16816(float* d, const uint32_t* a, uint32_t b0, uint32_t b1) {
    asm volatile("mma.sync.aligned.m16n8k16.row.col.f32.f16.f16.f32 "
                 "{%0,%1,%2,%3}, {%4,%5,%6,%7}, {%8,%9}, {%0,%1,%2,%3};"
                 : "+f"(d[0]), "+f"(d[1]), "+f"(d[2]), "+f"(d[3])
                 : "r"(a[0]), "r"(a[1]), "r"(a[2]), "r"(a[3]), "r"(b0), "r"(b1));
}
__device__ __forceinline__ void cpa16(uint32_t dst, const void* src) {
    asm volatile("cp.async.cg.shared.global [%0], [%1], 16;" :: "r"(dst), "l"(src));
}
__device__ __forceinline__ void cpa_commit() { asm volatile("cp.async.commit_group;"); }

// ---------------- fp32 -> fp16 conversion into static scratch ----------------
__global__ void f2h_kernel(const float* __restrict__ s, int sel, int n) {
    __half* d = (sel == 0) ? g_obs : ((sel == 1) ? g_W1 : g_W2);
    int i = (blockIdx.x * blockDim.x + threadIdx.x) * 4;
    if (i >= n) return;
    float4 v = *(const float4*)(s + i);
    *(__half2*)(d + i)     = __floats2half2_rn(v.x, v.y);
    *(__half2*)(d + i + 2) = __floats2half2_rn(v.z, v.w);
}

// ---------------- mu init: mu[b][a] = b3[a] ----------------
__global__ void mu_init_kernel(const float* __restrict__ b3, float* __restrict__ mu) {
    int i = blockIdx.x * blockDim.x + threadIdx.x;     // 0 .. BATCH*ACT-1
    if (i < BATCH * ACT) mu[i] = b3[i & 31];
}

// ---------------- batched GEMM + bias + tanh, 4-stage cp.async pipeline -------
// Tile: 128x128x32, 256 threads, 8 warps as 4(m) x 2(n), warp tile 32x64.
// L1 == true : C = tanh(obs @ W1[a] + b1[a]) stored fp16 into g_x1
// L1 == false: fused layer-3. No C store; epilogue computes
//              partial mu[m][a] += sum_n tanh(x1@W2+b2) * W3[a][n] via atomicAdd.
//
// Dynamic smem layout (bytes):
//   sA: 4 stages * 128 * 40 halves  = 40960
//   sB: 4 stages *  32 * 136 halves = 34816   (offset 40960)
//   sBias: 128 floats                (offset 75776)
//   sW3:   128 floats                (offset 76288)
#define SMEM_BYTES 76800

template <int K, bool IS_L1>
__global__ void __launch_bounds__(256, 2) gemm_kernel(const float* __restrict__ bias,
                                                      const float* __restrict__ W3,
                                                      float* __restrict__ mu) {
    constexpr int BK = 32;
    extern __shared__ char smem[];
    auto sA    = (__half (*)[128][BK + 8])(smem);
    auto sB    = (__half (*)[BK][128 + 8])(smem + 40960);
    float* sBias = (float*)(smem + 75776);
    float* sW3   = (float*)(smem + 76288);

    const int a  = blockIdx.z;
    const int m0 = blockIdx.y * 128;
    const int n0 = blockIdx.x * 128;

    const __half* A  = IS_L1 ? (g_obs + (size_t)m0 * K)
                             : (g_x1 + ((size_t)a * BATCH + m0) * K);
    const __half* Bw = (IS_L1 ? g_W1 : g_W2) + (size_t)a * K * 1024 + n0;

    const int t = threadIdx.x;
    if (t < 128) {
        sBias[t] = bias[a * 1024 + n0 + t];
        if (!IS_L1) sW3[t] = W3[a * 1024 + n0 + t];
    }

    auto load = [&](int s, int kt) {
#pragma unroll
        for (int i = 0; i < 2; i++) {                       // A: 128 rows x 32 halves
            int c = t + i * 256;
            int r = c >> 2, c8 = (c & 3) * 8;
            cpa16(s32(&sA[s][r][c8]), A + (size_t)r * K + kt + c8);
        }
#pragma unroll
        for (int i = 0; i < 2; i++) {                       // B: 32 rows x 128 halves
            int c = t + i * 256;
            int r = c >> 4, c8 = (c & 15) * 8;
            cpa16(s32(&sB[s][r][c8]), Bw + (size_t)(kt + r) * 1024 + c8);
        }
    };

    const int lane = t & 31, warp = t >> 5;
    const int wm = warp >> 1, wn = warp & 1;

    float acc[2][8][4];
#pragma unroll
    for (int mi = 0; mi < 2; mi++)
#pragma unroll
        for (int ni = 0; ni < 8; ni++)
#pragma unroll
            for (int k = 0; k < 4; k++) acc[mi][ni][k] = 0.f;

    constexpr int NK = K / BK;

    // prologue: fill 3 of 4 stages
#pragma unroll
    for (int p = 0; p < 3; p++) { load(p, p * BK); cpa_commit(); }

    const int lrow  = lane & 15;
    const int lc8   = (lane >> 4) * 8;
    const int bkrow = lane & 7;
    const int bk8   = ((lane >> 3) & 1) * 8;
    const int bn8   = (lane >> 4) * 8;

    for (int kt = 0; kt < NK; kt++) {
        const int s = kt & 3;
        asm volatile("cp.async.wait_group 2;");   // stage kt's group complete
        __syncthreads();                          // all warps done with stage (kt-1)&3
        if (kt + 3 < NK) load((kt + 3) & 3, (kt + 3) * BK);
        cpa_commit();                             // one group per iter (may be empty)

#pragma unroll
        for (int ks = 0; ks < 2; ks++) {
            uint32_t af[2][4];
#pragma unroll
            for (int mi = 0; mi < 2; mi++)
                ldm_x4(af[mi], s32(&sA[s][wm * 32 + mi * 16 + lrow][ks * 16 + lc8]));
            uint32_t bf[4][4];
#pragma unroll
            for (int np = 0; np < 4; np++)
                ldm_x4t(bf[np], s32(&sB[s][ks * 16 + bk8 + bkrow][wn * 64 + np * 16 + bn8]));
#pragma unroll
            for (int mi = 0; mi < 2; mi++)
#pragma unroll
                for (int ni = 0; ni < 8; ni++) {
                    int np = ni >> 1, h = (ni & 1) * 2;
                    mma16816(acc[mi][ni], af[mi], bf[np][h], bf[np][h + 1]);
                }
        }
    }

    // ---------------- epilogue ----------------
    if (IS_L1) {
        __half* C = g_x1 + ((size_t)a * BATCH + m0) * 1024 + n0;
#pragma unroll
        for (int mi = 0; mi < 2; mi++) {
            int r0 = wm * 32 + mi * 16 + (lane >> 2);
#pragma unroll
            for (int ni = 0; ni < 8; ni++) {
                int cl = wn * 64 + ni * 8 + (lane & 3) * 2;
                float b0 = sBias[cl], b1 = sBias[cl + 1];
                float* d = acc[mi][ni];
                __half2 h0 = __floats2half2_rn(tanhf(d[0] + b0), tanhf(d[1] + b1));
                __half2 h1 = __floats2half2_rn(tanhf(d[2] + b0), tanhf(d[3] + b1));
                *(__half2*)(C + (size_t)r0 * 1024 + cl)       = h0;
                *(__half2*)(C + (size_t)(r0 + 8) * 1024 + cl) = h1;
            }
        }
    } else {
        // fused layer-3: pmu[mi][h] = partial dot over this warp's 64 columns
        float pmu[2][2] = {{0.f, 0.f}, {0.f, 0.f}};
#pragma unroll
        for (int mi = 0; mi < 2; mi++)
#pragma unroll
            for (int ni = 0; ni < 8; ni++) {
                int cl = wn * 64 + ni * 8 + (lane & 3) * 2;
                float b0 = sBias[cl], b1 = sBias[cl + 1];
                float w0 = sW3[cl],   w1 = sW3[cl + 1];
                float* d = acc[mi][ni];
                pmu[mi][0] += tanhf(d[0] + b0) * w0 + tanhf(d[1] + b1) * w1;
                pmu[mi][1] += tanhf(d[2] + b0) * w0 + tanhf(d[3] + b1) * w1;
            }
        // reduce across the 4 lanes of each quad (same row, different col pairs)
#pragma unroll
        for (int o = 1; o <= 2; o <<= 1)
#pragma unroll
            for (int mi = 0; mi < 2; mi++) {
                pmu[mi][0] += __shfl_xor_sync(0xffffffffu, pmu[mi][0], o);
                pmu[mi][1] += __shfl_xor_sync(0xffffffffu, pmu[mi][1], o);
            }
        if ((lane & 3) == 0) {
#pragma unroll
            for (int mi = 0; mi < 2; mi++) {
                int row = m0 + wm * 32 + mi * 16 + (lane >> 2);
                atomicAdd(mu + (size_t)row * 32 + a, pmu[mi][0]);
                atomicAdd(mu + (size_t)(row + 8) * 32 + a, pmu[mi][1]);
            }
        }
    }
}

// ---------------- logp --------------------------------------------------------
__global__ void logp_kernel(const float* __restrict__ mu, const float* __restrict__ act,
                            const float* __restrict__ ls, float* __restrict__ lp) {
    int b = blockIdx.x * blockDim.x + threadIdx.x;
    if (b >= BATCH) return;
    float s = 0.f;
#pragma unroll
    for (int a = 0; a < 32; a++) {
        float l = ls[a];
        float z = (act[b * 32 + a] - mu[b * 32 + a]) * expf(-l);
        s += -0.5f * (z * z + 1.8378770664093453f) - l;
    }
    lp[b] = s;
}

// ---------------- launch ------------------------------------------------------
extern "C" void kernel_launch(void* const* d_in, const int* in_sizes, int n_in,
                              void* d_out, int out_size) {
    const float* obs  = (const float*)d_in[0];
    const float* act  = (const float*)d_in[1];
    const float* W1   = (const float*)d_in[2];
    const float* b1   = (const float*)d_in[3];
    const float* W2   = (const float*)d_in[4];
    const float* b2   = (const float*)d_in[5];
    const float* W3   = (const float*)d_in[6];
    const float* b3   = (const float*)d_in[7];
    const float* lstd = (const float*)d_in[8];

    float* out = (float*)d_out;
    float* mu  = out;                              // [4096][32]
    float* lp  = out + (size_t)BATCH * ACT;        // [4096]

    static bool attr_done = false;
    if (!attr_done) {
        cudaFuncSetAttribute(gemm_kernel<OBS, true>,
                             cudaFuncAttributeMaxDynamicSharedMemorySize, SMEM_BYTES);
        cudaFuncSetAttribute(gemm_kernel<H1D, false>,
                             cudaFuncAttributeMaxDynamicSharedMemorySize, SMEM_BYTES);
        attr_done = true;
    }

    f2h_kernel<<<(BATCH * OBS) / 1024, 256>>>(obs, 0, BATCH * OBS);
    f2h_kernel<<<(ACT * OBS * H1D) / 1024, 256>>>(W1, 1, ACT * OBS * H1D);
    f2h_kernel<<<(ACT * H1D * H2D) / 1024, 256>>>(W2, 2, ACT * H1D * H2D);

    mu_init_kernel<<<(BATCH * ACT) / 256, 256>>>(b3, mu);

    gemm_kernel<OBS, true><<<dim3(8, 32, 32), 256, SMEM_BYTES>>>(b1, nullptr, nullptr);
    gemm_kernel<H1D, false><<<dim3(8, 32, 32), 256, SMEM_BYTES>>>(b2, W3, mu);

    logp_kernel<<<(BATCH + 255) / 256, 256>>>(mu, act, lstd, lp);
}

// round 5
// speedup vs baseline: 1.1373x; 1.0749x over previous
#include <cuda_runtime.h>
#include <cuda_fp16.h>
#include <cstdint>
#include <cstddef>

#define BATCH 4096
#define OBS   512
#define ACT   32
#define H1D   1024
#define H2D   1024

// ---------------- static device scratch (no allocations) ----------------
static __device__ __align__(256) __half g_obs[(size_t)BATCH * OBS];           //   4 MB
static __device__ __align__(256) __half g_W1 [(size_t)ACT * OBS * H1D];       //  32 MB
static __device__ __align__(256) __half g_W2 [(size_t)ACT * H1D * H2D];       //  64 MB
static __device__ __align__(256) __half g_x1 [(size_t)ACT * BATCH * H1D];     // 256 MB

// ---------------- PTX helpers ----------------
__device__ __forceinline__ uint32_t s32(const void* p) {
    return (uint32_t)__cvta_generic_to_shared(p);
}
__device__ __forceinline__ void ldm_x4(uint32_t* r, uint32_t a) {
    asm volatile("ldmatrix.sync.aligned.m8n8.x4.shared.b16 {%0,%1,%2,%3}, [%4];"
                 : "=r"(r[0]), "=r"(r[1]), "=r"(r[2]), "=r"(r[3]) : "r"(a));
}
__device__ __forceinline__ void ldm_x4t(uint32_t* r, uint32_t a) {
    asm volatile("ldmatrix.sync.aligned.m8n8.x4.trans.shared.b16 {%0,%1,%2,%3}, [%4];"
                 : "=r"(r[0]), "=r"(r[1]), "=r"(r[2]), "=r"(r[3]) : "r"(a));
}
__device__ __forceinline__ void mma16816(float* d, const uint32_t* a, uint32_t b0, uint32_t b1) {
    asm volatile("mma.sync.aligned.m16n8k16.row.col.f32.f16.f16.f32 "
                 "{%0,%1,%2,%3}, {%4,%5,%6,%7}, {%8,%9}, {%0,%1,%2,%3};"
                 : "+f"(d[0]), "+f"(d[1]), "+f"(d[2]), "+f"(d[3])
                 : "r"(a[0]), "r"(a[1]), "r"(a[2]), "r"(a[3]), "r"(b0), "r"(b1));
}
__device__ __forceinline__ void cpa16(uint32_t dst, const void* src) {
    asm volatile("cp.async.cg.shared.global [%0], [%1], 16;" :: "r"(dst), "l"(src));
}
__device__ __forceinline__ void cpa_commit() { asm volatile("cp.async.commit_group;"); }

// ---------------- fp32 -> fp16 conversion into static scratch ----------------
__global__ void f2h_kernel(const float* __restrict__ s, int sel, int n) {
    __half* d = (sel == 0) ? g_obs : ((sel == 1) ? g_W1 : g_W2);
    int i = (blockIdx.x * blockDim.x + threadIdx.x) * 4;
    if (i >= n) return;
    float4 v = *(const float4*)(s + i);
    *(__half2*)(d + i)     = __floats2half2_rn(v.x, v.y);
    *(__half2*)(d + i + 2) = __floats2half2_rn(v.z, v.w);
}

// ---------------- mu init: mu[b][a] = b3[a] ----------------
__global__ void mu_init_kernel(const float* __restrict__ b3, float* __restrict__ mu) {
    int i = blockIdx.x * blockDim.x + threadIdx.x;     // 0 .. BATCH*ACT-1
    if (i < BATCH * ACT) mu[i] = b3[i & 31];
}

// ---------------- batched GEMM + bias + tanh, BK=64, 3-stage pipeline ---------
// Tile: 128x128x64, 256 threads, 8 warps as 4(m) x 2(n), warp tile 32x64.
// IS_L1 == true : C = tanh(obs @ W1[a] + b1[a]) stored fp16 into g_x1
// IS_L1 == false: fused layer-3; epilogue does mu[m][a] += sum_n tanh(.)*W3[a][n]
//
// Dynamic smem (bytes):
//   sA: 3 stages * 128 * 72 halves = 55296
//   sB: 3 stages *  64 * 136 halves = 52224  (offset 55296)
//   sBias: 128 floats (offset 107520)
//   sW3:   128 floats (offset 108032)
#define SMEM_BYTES 108544

template <int K, bool IS_L1>
__global__ void __launch_bounds__(256, 2) gemm_kernel(const float* __restrict__ bias,
                                                      const float* __restrict__ W3,
                                                      float* __restrict__ mu) {
    constexpr int BK = 64;
    extern __shared__ char smem[];
    auto sA    = (__half (*)[128][BK + 8])(smem);
    auto sB    = (__half (*)[BK][128 + 8])(smem + 55296);
    float* sBias = (float*)(smem + 107520);
    float* sW3   = (float*)(smem + 108032);

    const int a  = blockIdx.z;
    const int m0 = blockIdx.y * 128;
    const int n0 = blockIdx.x * 128;

    const __half* A  = IS_L1 ? (g_obs + (size_t)m0 * K)
                             : (g_x1 + ((size_t)a * BATCH + m0) * K);
    const __half* Bw = (IS_L1 ? g_W1 : g_W2) + (size_t)a * K * 1024 + n0;

    const int t = threadIdx.x;
    if (t < 128) {
        sBias[t] = bias[a * 1024 + n0 + t];
        if (!IS_L1) sW3[t] = W3[a * 1024 + n0 + t];
    }

    auto load = [&](int s, int kt) {
#pragma unroll
        for (int i = 0; i < 4; i++) {                       // A: 128 rows x 64 halves
            int c = t + i * 256;
            int r = c >> 3, c8 = (c & 7) * 8;
            cpa16(s32(&sA[s][r][c8]), A + (size_t)r * K + kt + c8);
        }
#pragma unroll
        for (int i = 0; i < 4; i++) {                       // B: 64 rows x 128 halves
            int c = t + i * 256;
            int r = c >> 4, c8 = (c & 15) * 8;
            cpa16(s32(&sB[s][r][c8]), Bw + (size_t)(kt + r) * 1024 + c8);
        }
    };

    const int lane = t & 31, warp = t >> 5;
    const int wm = warp >> 1, wn = warp & 1;

    float acc[2][8][4];
#pragma unroll
    for (int mi = 0; mi < 2; mi++)
#pragma unroll
        for (int ni = 0; ni < 8; ni++)
#pragma unroll
            for (int k = 0; k < 4; k++) acc[mi][ni][k] = 0.f;

    constexpr int NK = K / BK;

    // prologue: fill 2 of 3 stages
    load(0, 0);            cpa_commit();
    if (NK > 1) load(1, BK);
    cpa_commit();

    const int lrow  = lane & 15;
    const int lc8   = (lane >> 4) * 8;
    const int bkrow = lane & 7;
    const int bk8   = ((lane >> 3) & 1) * 8;
    const int bn8   = (lane >> 4) * 8;

    int s = 0;
    for (int kt = 0; kt < NK; kt++) {
        asm volatile("cp.async.wait_group 1;");   // stage kt's group complete
        __syncthreads();                          // everyone done with stage being reused
        if (kt + 2 < NK) load((s + 2) % 3, (kt + 2) * BK);
        cpa_commit();                             // one group per iter (may be empty)

#pragma unroll
        for (int ks = 0; ks < 4; ks++) {          // four k16 steps per BK=64
            uint32_t af[2][4];
#pragma unroll
            for (int mi = 0; mi < 2; mi++)
                ldm_x4(af[mi], s32(&sA[s][wm * 32 + mi * 16 + lrow][ks * 16 + lc8]));
            uint32_t bf[4][4];
#pragma unroll
            for (int np = 0; np < 4; np++)
                ldm_x4t(bf[np], s32(&sB[s][ks * 16 + bk8 + bkrow][wn * 64 + np * 16 + bn8]));
#pragma unroll
            for (int mi = 0; mi < 2; mi++)
#pragma unroll
                for (int ni = 0; ni < 8; ni++) {
                    int np = ni >> 1, h = (ni & 1) * 2;
                    mma16816(acc[mi][ni], af[mi], bf[np][h], bf[np][h + 1]);
                }
        }
        s = (s + 1) % 3;
    }

    // ---------------- epilogue ----------------
    if (IS_L1) {
        __half* C = g_x1 + ((size_t)a * BATCH + m0) * 1024 + n0;
#pragma unroll
        for (int mi = 0; mi < 2; mi++) {
            int r0 = wm * 32 + mi * 16 + (lane >> 2);
#pragma unroll
            for (int ni = 0; ni < 8; ni++) {
                int cl = wn * 64 + ni * 8 + (lane & 3) * 2;
                float b0 = sBias[cl], b1 = sBias[cl + 1];
                float* d = acc[mi][ni];
                __half2 h0 = __floats2half2_rn(tanhf(d[0] + b0), tanhf(d[1] + b1));
                __half2 h1 = __floats2half2_rn(tanhf(d[2] + b0), tanhf(d[3] + b1));
                *(__half2*)(C + (size_t)r0 * 1024 + cl)       = h0;
                *(__half2*)(C + (size_t)(r0 + 8) * 1024 + cl) = h1;
            }
        }
    } else {
        float pmu[2][2] = {{0.f, 0.f}, {0.f, 0.f}};
#pragma unroll
        for (int mi = 0; mi < 2; mi++)
#pragma unroll
            for (int ni = 0; ni < 8; ni++) {
                int cl = wn * 64 + ni * 8 + (lane & 3) * 2;
                float b0 = sBias[cl], b1 = sBias[cl + 1];
                float w0 = sW3[cl],   w1 = sW3[cl + 1];
                float* d = acc[mi][ni];
                pmu[mi][0] += tanhf(d[0] + b0) * w0 + tanhf(d[1] + b1) * w1;
                pmu[mi][1] += tanhf(d[2] + b0) * w0 + tanhf(d[3] + b1) * w1;
            }
#pragma unroll
        for (int o = 1; o <= 2; o <<= 1)
#pragma unroll
            for (int mi = 0; mi < 2; mi++) {
                pmu[mi][0] += __shfl_xor_sync(0xffffffffu, pmu[mi][0], o);
                pmu[mi][1] += __shfl_xor_sync(0xffffffffu, pmu[mi][1], o);
            }
        if ((lane & 3) == 0) {
#pragma unroll
            for (int mi = 0; mi < 2; mi++) {
                int row = m0 + wm * 32 + mi * 16 + (lane >> 2);
                atomicAdd(mu + (size_t)row * 32 + a, pmu[mi][0]);
                atomicAdd(mu + (size_t)(row + 8) * 32 + a, pmu[mi][1]);
            }
        }
    }
}

// ---------------- logp --------------------------------------------------------
__global__ void logp_kernel(const float* __restrict__ mu, const float* __restrict__ act,
                            const float* __restrict__ ls, float* __restrict__ lp) {
    int b = blockIdx.x * blockDim.x + threadIdx.x;
    if (b >= BATCH) return;
    float s = 0.f;
#pragma unroll
    for (int a = 0; a < 32; a++) {
        float l = ls[a];
        float z = (act[b * 32 + a] - mu[b * 32 + a]) * expf(-l);
        s += -0.5f * (z * z + 1.8378770664093453f) - l;
    }
    lp[b] = s;
}

// ---------------- launch ------------------------------------------------------
extern "C" void kernel_launch(void* const* d_in, const int* in_sizes, int n_in,
                              void* d_out, int out_size) {
    const float* obs  = (const float*)d_in[0];
    const float* act  = (const float*)d_in[1];
    const float* W1   = (const float*)d_in[2];
    const float* b1   = (const float*)d_in[3];
    const float* W2   = (const float*)d_in[4];
    const float* b2   = (const float*)d_in[5];
    const float* W3   = (const float*)d_in[6];
    const float* b3   = (const float*)d_in[7];
    const float* lstd = (const float*)d_in[8];

    float* out = (float*)d_out;
    float* mu  = out;                              // [4096][32]
    float* lp  = out + (size_t)BATCH * ACT;        // [4096]

    static bool attr_done = false;
    if (!attr_done) {
        cudaFuncSetAttribute(gemm_kernel<OBS, true>,
                             cudaFuncAttributeMaxDynamicSharedMemorySize, SMEM_BYTES);
        cudaFuncSetAttribute(gemm_kernel<H1D, false>,
                             cudaFuncAttributeMaxDynamicSharedMemorySize, SMEM_BYTES);
        attr_done = true;
    }

    f2h_kernel<<<(BATCH * OBS) / 1024, 256>>>(obs, 0, BATCH * OBS);
    f2h_kernel<<<(ACT * OBS * H1D) / 1024, 256>>>(W1, 1, ACT * OBS * H1D);
    f2h_kernel<<<(ACT * H1D * H2D) / 1024, 256>>>(W2, 2, ACT * H1D * H2D);

    mu_init_kernel<<<(BATCH * ACT) / 256, 256>>>(b3, mu);

    gemm_kernel<OBS, true><<<dim3(8, 32, 32), 256, SMEM_BYTES>>>(b1, nullptr, nullptr);
    gemm_kernel<H1D, false><<<dim3(8, 32, 32), 256, SMEM_BYTES>>>(b2, W3, mu);

    logp_kernel<<<(BATCH + 255) / 256, 256>>>(mu, act, lstd, lp);
}